// round 6
// baseline (speedup 1.0000x reference)
#include <cuda_runtime.h>
#include <cuda_bf16.h>
#include <math.h>
#include <stdint.h>

#define NB   8
#define TT   4096
#define CC   768
#define HIDD 3072
#define MTOT (NB * TT)      /* 32768 */
#define ADA6 (6 * CC)       /* 4608  */

// ---------------- scratch (static device globals; allocation-free) ----------
__device__ float g_ada[NB * ADA6];
__device__ float g_x  [(size_t)MTOT * CC];
__device__ __nv_bfloat16 g_hb  [(size_t)MTOT * CC];     // LN+mod output (bf16)
__device__ __nv_bfloat16 g_qkvb[(size_t)MTOT * 3 * CC]; // qkv (bf16)
__device__ __nv_bfloat16 g_attb[(size_t)MTOT * CC];     // attention out (bf16)
__device__ __nv_bfloat16 g_hidb[(size_t)MTOT * HIDD];   // MLP hidden (bf16)
__device__ __nv_bfloat16 g_wqb[3 * CC * CC];
__device__ __nv_bfloat16 g_wpb[CC * CC];
__device__ __nv_bfloat16 g_w1b[HIDD * CC];
__device__ __nv_bfloat16 g_w2b[CC * HIDD];

// ---------------- helpers ----------------------------------------------------
__device__ __forceinline__ uint32_t smem_u32(const void* p) {
    uint32_t a;
    asm("{ .reg .u64 t; cvta.to.shared.u64 t, %1; cvt.u32.u64 %0, t; }"
        : "=r"(a) : "l"(p));
    return a;
}

__device__ __forceinline__ void mma_bf16(float* d, const uint32_t* a, const uint32_t* b) {
    asm volatile(
        "mma.sync.aligned.m16n8k16.row.col.f32.bf16.bf16.f32 "
        "{%0,%1,%2,%3}, {%4,%5,%6,%7}, {%8,%9}, {%0,%1,%2,%3};"
        : "+f"(d[0]), "+f"(d[1]), "+f"(d[2]), "+f"(d[3])
        : "r"(a[0]), "r"(a[1]), "r"(a[2]), "r"(a[3]), "r"(b[0]), "r"(b[1]));
}

#define LDMX4(r0, r1, r2, r3, addr)                                           \
    asm volatile("ldmatrix.sync.aligned.m8n8.x4.shared.b16 {%0,%1,%2,%3}, [%4];" \
                 : "=r"(r0), "=r"(r1), "=r"(r2), "=r"(r3) : "r"(addr))

__device__ __forceinline__ uint32_t packbf(float lo, float hi) {
    __nv_bfloat162 h = __floats2bfloat162_rn(lo, hi);
    return *(uint32_t*)&h;
}

// window(m) -> sequence row index (inverse shift + unpartition)
__device__ __forceinline__ int win2seq(int m) {
    const int nbat = m >> 12, rem = m & 4095, win = rem >> 6, t = rem & 63;
    const int gh = ((win >> 3) << 3) + (t >> 3);
    const int gw = ((win & 7) << 3) + (t & 7);
    return nbat * TT + ((((gh + 4) & 63) << 6) | ((gw + 4) & 63));
}

// ---------------- bf16 mma.sync GEMM (NT): C[M,N]=A[M,K]@B[N,K]^T + bias ----
// CTA 128x128x32, 4-stage cp.async, 8 warps (2x4), warp tile 64x32, ldmatrix.
// EPI 0: -> bf16 (qkv). 1: gate + scatter-residual -> fp32 (proj).
// EPI 2: tanh-GELU -> bf16 (fc1). 3: resid + gate -> fp32 (fc2/out).
#define GSTRIDE 20
#define STG_U   (128 * GSTRIDE)
#define NSTG    4
#define MM_SMEM_BYTES (2 * NSTG * STG_U * 4)

template <int EPI>
__global__ void __launch_bounds__(256, 2) mm_gemm(
    const __nv_bfloat16* __restrict__ A, const __nv_bfloat16* __restrict__ B,
    const float* __restrict__ bias, void* __restrict__ Cv,
    int N, int K, const float* __restrict__ gate, const float* __restrict__ resid)
{
    extern __shared__ uint32_t sm[];
    const uint32_t smb = smem_u32(sm);
    const uint32_t BOFF = NSTG * STG_U * 4;
    const int tid = threadIdx.x;
    const int lane = tid & 31, wid = tid >> 5;
    const int g = lane >> 2, t4 = lane & 3;
    const int warpM = wid >> 2, warpN = wid & 3;
    const int n0 = blockIdx.x * 128, m0 = blockIdx.y * 128;
    const int nk = K >> 5;

    // ldmatrix per-lane source row/col (same mapping for A and B tiles)
    const int matq = lane >> 3, rowq = lane & 7;
    const int lmRow = ((matq & 1) << 3) + rowq;      // row within 16-row tile
    const int lmCol = (matq >> 1) << 2;              // u32 col (0 or 4)

    float acc[4][4][4];
    #pragma unroll
    for (int i = 0; i < 4; i++)
        #pragma unroll
        for (int j = 0; j < 4; j++)
            #pragma unroll
            for (int q = 0; q < 4; q++) acc[i][j][q] = 0.0f;

    auto load_stage = [&](int s, int kk) {
        const int k0 = kk << 5;
        #pragma unroll
        for (int j = 0; j < 2; j++) {
            const int f = tid + (j << 8);
            const int r = f >> 2, q = f & 3;
            const __nv_bfloat16* srcA = A + (size_t)(m0 + r) * K + k0 + (q << 3);
            const __nv_bfloat16* srcB = B + (size_t)(n0 + r) * K + k0 + (q << 3);
            const uint32_t off = (uint32_t)(s * STG_U + r * GSTRIDE + (q << 2)) << 2;
            asm volatile("cp.async.cg.shared.global [%0], [%1], 16;"
                         :: "r"(smb + off), "l"(srcA));
            asm volatile("cp.async.cg.shared.global [%0], [%1], 16;"
                         :: "r"(smb + BOFF + off), "l"(srcB));
        }
        asm volatile("cp.async.commit_group;" ::: "memory");
    };

    load_stage(0, 0);
    load_stage(1, 1);
    load_stage(2, 2);

    // per-lane ldmatrix byte offsets (within a stage)
    const uint32_t aBase = smb +
        (uint32_t)((warpM * 64 + lmRow) * GSTRIDE + lmCol) * 4u;
    const uint32_t bBase = smb + BOFF +
        (uint32_t)((warpN * 32 + lmRow) * GSTRIDE + lmCol) * 4u;

    int s = 0;
    for (int kk = 0; kk < nk; kk++) {
        if (kk + 1 < nk) asm volatile("cp.async.wait_group 2;" ::: "memory");
        else             asm volatile("cp.async.wait_group 0;" ::: "memory");
        __syncthreads();
        if (kk + 3 < nk) load_stage((s + 3) & 3, kk + 3);

        const uint32_t sOff = (uint32_t)(s * STG_U) * 4u;
        #pragma unroll
        for (int ks = 0; ks < 2; ks++) {
            const uint32_t kOff = sOff + (uint32_t)(ks << 5);   // ks*8 u32
            uint32_t a[4][4], b[4][2];
            #pragma unroll
            for (int i = 0; i < 4; i++) {
                LDMX4(a[i][0], a[i][1], a[i][2], a[i][3],
                      aBase + kOff + (uint32_t)(i * 16 * GSTRIDE * 4));
            }
            #pragma unroll
            for (int p = 0; p < 2; p++) {
                LDMX4(b[2 * p][0], b[2 * p + 1][0], b[2 * p][1], b[2 * p + 1][1],
                      bBase + kOff + (uint32_t)(p * 16 * GSTRIDE * 4));
            }
            #pragma unroll
            for (int i = 0; i < 4; i++)
                #pragma unroll
                for (int j = 0; j < 4; j++)
                    mma_bf16(acc[i][j], a[i], b[j]);
        }
        s = (s + 1) & 3;
    }

    // ---------------- epilogue ------------------------------------------------
    const int batch = m0 >> 12;
    const float* gbase = (EPI == 1 || EPI == 3) ? (gate + batch * ADA6) : nullptr;
    #pragma unroll
    for (int i = 0; i < 4; i++) {
        #pragma unroll
        for (int h2 = 0; h2 < 2; h2++) {
            const int row = m0 + warpM * 64 + i * 16 + g + h2 * 8;
            const int srow = (EPI == 1) ? win2seq(row) : row;
            const float* rrow = (EPI == 1 || EPI == 3)
                                ? (resid + (size_t)srow * N) : nullptr;
            #pragma unroll
            for (int j = 0; j < 4; j++) {
                const int nc = n0 + warpN * 32 + j * 8 + t4 * 2;
                float v0 = acc[i][j][h2 * 2 + 0] + bias[nc];
                float v1 = acc[i][j][h2 * 2 + 1] + bias[nc + 1];
                if (EPI == 1) {
                    v0 = rrow[nc]     + gbase[nc]     * v0;
                    v1 = rrow[nc + 1] + gbase[nc + 1] * v1;
                } else if (EPI == 2) {
                    float u0 = 0.7978845608028654f * (v0 + 0.044715f * v0 * v0 * v0);
                    float u1 = 0.7978845608028654f * (v1 + 0.044715f * v1 * v1 * v1);
                    v0 = __fdividef(v0, 1.0f + __expf(-2.0f * u0));
                    v1 = __fdividef(v1, 1.0f + __expf(-2.0f * u1));
                } else if (EPI == 3) {
                    v0 = rrow[nc]     + gbase[nc]     * v0;
                    v1 = rrow[nc + 1] + gbase[nc + 1] * v1;
                }
                if (EPI == 0 || EPI == 2) {
                    __nv_bfloat16* crow = (__nv_bfloat16*)Cv + (size_t)row * N;
                    __nv_bfloat162 h = __floats2bfloat162_rn(v0, v1);
                    *(__nv_bfloat162*)(crow + nc) = h;
                } else {
                    float* crow = (float*)Cv + (size_t)srow * N;
                    *(float2*)(crow + nc) = make_float2(v0, v1);
                }
            }
        }
    }
}

// ---------------- weight fp32 -> bf16 (rn) -----------------------------------
__global__ void __launch_bounds__(256) cvtw_kernel(
    const float* __restrict__ src, __nv_bfloat16* __restrict__ dst, int n4)
{
    const int i = blockIdx.x * 256 + threadIdx.x;
    if (i >= n4) return;
    float4 v = ((const float4*)src)[i];
    ((__nv_bfloat162*)dst)[i * 2]     = __floats2bfloat162_rn(v.x, v.y);
    ((__nv_bfloat162*)dst)[i * 2 + 1] = __floats2bfloat162_rn(v.z, v.w);
}

// ---------------- adaLN: ada = silu(c) @ ada_w^T + ada_b --------------------
__global__ void __launch_bounds__(128) ada_kernel(
    const float* __restrict__ c, const float* __restrict__ w,
    const float* __restrict__ b, float* __restrict__ ada)
{
    __shared__ float sc[CC];
    const int n = blockIdx.x, tid = threadIdx.x;
    for (int i = tid; i < CC; i += 128) {
        float x = c[n * CC + i];
        sc[i] = x / (1.0f + expf(-x));
    }
    __syncthreads();
    const int j = blockIdx.y * 128 + tid;
    const float* wr = w + (size_t)j * CC;
    float acc = b[j];
    #pragma unroll 8
    for (int k = 0; k < CC; k++) acc += sc[k] * wr[k];
    ada[n * ADA6 + j] = acc;
}

// ---------------- LN + modulate -> bf16 ---------------------------------------
template <int MODE>
__global__ void __launch_bounds__(256) ln_mod_kernel(
    const float* __restrict__ xin, const float* __restrict__ ada,
    __nv_bfloat16* __restrict__ out)
{
    const int m = blockIdx.x, tid = threadIdx.x;
    const int n = m >> 12;
    const float* xr;
    if (MODE == 0) {
        xr = xin + (size_t)win2seq(m) * CC;
    } else {
        xr = xin + (size_t)m * CC;
    }
    float v0 = xr[tid], v1 = xr[tid + 256], v2 = xr[tid + 512];
    __shared__ float rs[256], rq[256];
    rs[tid] = v0 + v1 + v2;
    rq[tid] = v0 * v0 + v1 * v1 + v2 * v2;
    __syncthreads();
    #pragma unroll
    for (int off = 128; off > 0; off >>= 1) {
        if (tid < off) { rs[tid] += rs[tid + off]; rq[tid] += rq[tid + off]; }
        __syncthreads();
    }
    const float mean = rs[0] * (1.0f / CC);
    const float var  = rq[0] * (1.0f / CC) - mean * mean;
    const float rstd = rsqrtf(var + 1e-6f);
    const float* shv = ada + n * ADA6 + (MODE == 0 ? 0 : 3 * CC);
    const float* scv = ada + n * ADA6 + (MODE == 0 ? CC : 4 * CC);
    const size_t ob = (size_t)m * CC;
    out[ob + tid      ] = __float2bfloat16_rn((v0 - mean) * rstd * (1.0f + scv[tid      ]) + shv[tid      ]);
    out[ob + tid + 256] = __float2bfloat16_rn((v1 - mean) * rstd * (1.0f + scv[tid + 256]) + shv[tid + 256]);
    out[ob + tid + 512] = __float2bfloat16_rn((v2 - mean) * rstd * (1.0f + scv[tid + 512]) + shv[tid + 512]);
}

// ---------------- window attention (bf16 mma.sync) ---------------------------
#define APAD 72
__global__ void __launch_bounds__(128) attn_mma_kernel(
    const __nv_bfloat16* __restrict__ qkv, __nv_bfloat16* __restrict__ out)
{
    __shared__ __nv_bfloat16 sq [64 * APAD];
    __shared__ __nv_bfloat16 sk [64 * APAD];
    __shared__ __nv_bfloat16 svt[64 * APAD];   // V transposed: [d][c]
    const int b = blockIdx.x, hh = blockIdx.y;
    const int tid = threadIdx.x, lane = tid & 31, wid = tid >> 5;
    const int g = lane >> 2, t = lane & 3;
    const __nv_bfloat16* base = qkv + (size_t)b * 64 * (3 * CC) + hh * 64;

    {
        const int r = tid >> 1;
        const __nv_bfloat162 s8 = __floats2bfloat162_rn(0.125f, 0.125f);
        #pragma unroll
        for (int i = 0; i < 4; i++) {
            const int c0 = ((tid & 1) << 5) + (i << 3);
            uint4 vq = *(const uint4*)(base + (size_t)r * (3 * CC) + c0);
            __nv_bfloat162* pq = (__nv_bfloat162*)&vq;
            pq[0] = __hmul2(pq[0], s8); pq[1] = __hmul2(pq[1], s8);
            pq[2] = __hmul2(pq[2], s8); pq[3] = __hmul2(pq[3], s8);
            *(uint4*)(sq + r * APAD + c0) = vq;
            uint4 vk = *(const uint4*)(base + (size_t)r * (3 * CC) + CC + c0);
            *(uint4*)(sk + r * APAD + c0) = vk;
            uint4 vv = *(const uint4*)(base + (size_t)r * (3 * CC) + 2 * CC + c0);
            const __nv_bfloat16* hv = (const __nv_bfloat16*)&vv;
            #pragma unroll
            for (int q2 = 0; q2 < 8; q2++)
                svt[(c0 + q2) * APAD + r] = hv[q2];
        }
    }
    __syncthreads();

    const uint32_t* sq32 = (const uint32_t*)sq;
    const uint32_t* sk32 = (const uint32_t*)sk;
    const uint32_t* sv32 = (const uint32_t*)svt;
    const int mb = wid << 4;
    const int RS = APAD / 2;

    float accS[8][4];
    #pragma unroll
    for (int j = 0; j < 8; j++)
        #pragma unroll
        for (int q = 0; q < 4; q++) accS[j][q] = 0.0f;
    #pragma unroll
    for (int ks = 0; ks < 4; ks++) {
        const int kc = ks << 3;
        uint32_t a[4];
        a[0] = sq32[(mb + g    ) * RS + kc + t    ];
        a[1] = sq32[(mb + g + 8) * RS + kc + t    ];
        a[2] = sq32[(mb + g    ) * RS + kc + t + 4];
        a[3] = sq32[(mb + g + 8) * RS + kc + t + 4];
        #pragma unroll
        for (int j = 0; j < 8; j++) {
            uint32_t bb[2];
            bb[0] = sk32[((j << 3) + g) * RS + kc + t    ];
            bb[1] = sk32[((j << 3) + g) * RS + kc + t + 4];
            mma_bf16(accS[j], a, bb);
        }
    }

    float mx0 = -1e30f, mx1 = -1e30f;
    #pragma unroll
    for (int j = 0; j < 8; j++) {
        mx0 = fmaxf(mx0, fmaxf(accS[j][0], accS[j][1]));
        mx1 = fmaxf(mx1, fmaxf(accS[j][2], accS[j][3]));
    }
    mx0 = fmaxf(mx0, __shfl_xor_sync(0xffffffffu, mx0, 1));
    mx0 = fmaxf(mx0, __shfl_xor_sync(0xffffffffu, mx0, 2));
    mx1 = fmaxf(mx1, __shfl_xor_sync(0xffffffffu, mx1, 1));
    mx1 = fmaxf(mx1, __shfl_xor_sync(0xffffffffu, mx1, 2));
    float sum0 = 0.0f, sum1 = 0.0f;
    #pragma unroll
    for (int j = 0; j < 8; j++) {
        accS[j][0] = __expf(accS[j][0] - mx0);
        accS[j][1] = __expf(accS[j][1] - mx0);
        accS[j][2] = __expf(accS[j][2] - mx1);
        accS[j][3] = __expf(accS[j][3] - mx1);
        sum0 += accS[j][0] + accS[j][1];
        sum1 += accS[j][2] + accS[j][3];
    }
    sum0 += __shfl_xor_sync(0xffffffffu, sum0, 1);
    sum0 += __shfl_xor_sync(0xffffffffu, sum0, 2);
    sum1 += __shfl_xor_sync(0xffffffffu, sum1, 1);
    sum1 += __shfl_xor_sync(0xffffffffu, sum1, 2);
    const float inv0 = 1.0f / sum0, inv1 = 1.0f / sum1;

    uint32_t pa[4][4];
    #pragma unroll
    for (int ks = 0; ks < 4; ks++) {
        pa[ks][0] = packbf(accS[2 * ks][0],     accS[2 * ks][1]);
        pa[ks][1] = packbf(accS[2 * ks][2],     accS[2 * ks][3]);
        pa[ks][2] = packbf(accS[2 * ks + 1][0], accS[2 * ks + 1][1]);
        pa[ks][3] = packbf(accS[2 * ks + 1][2], accS[2 * ks + 1][3]);
    }

    float accO[8][4];
    #pragma unroll
    for (int j = 0; j < 8; j++)
        #pragma unroll
        for (int q = 0; q < 4; q++) accO[j][q] = 0.0f;
    #pragma unroll
    for (int ks = 0; ks < 4; ks++) {
        const int kc = ks << 3;
        #pragma unroll
        for (int j = 0; j < 8; j++) {
            uint32_t bb[2];
            bb[0] = sv32[((j << 3) + g) * RS + kc + t    ];
            bb[1] = sv32[((j << 3) + g) * RS + kc + t + 4];
            mma_bf16(accO[j], pa[ks], bb);
        }
    }

    __nv_bfloat16* orow0 = out + ((size_t)b * 64 + mb + g    ) * CC + hh * 64;
    __nv_bfloat16* orow1 = out + ((size_t)b * 64 + mb + g + 8) * CC + hh * 64;
    #pragma unroll
    for (int j = 0; j < 8; j++) {
        const int dc = (j << 3) + (t << 1);
        *(uint32_t*)(orow0 + dc) = packbf(accO[j][0] * inv0, accO[j][1] * inv0);
        *(uint32_t*)(orow1 + dc) = packbf(accO[j][2] * inv1, accO[j][3] * inv1);
    }
}

// ---------------- launch ------------------------------------------------------
extern "C" void kernel_launch(void* const* d_in, const int* in_sizes, int n_in,
                              void* d_out, int out_size)
{
    const float* x_seq  = (const float*)d_in[0];
    const float* c      = (const float*)d_in[1];
    const float* qkv_w  = (const float*)d_in[2];
    const float* qkv_b  = (const float*)d_in[3];
    const float* proj_w = (const float*)d_in[4];
    const float* proj_b = (const float*)d_in[5];
    const float* fc1_w  = (const float*)d_in[6];
    const float* fc1_b  = (const float*)d_in[7];
    const float* fc2_w  = (const float*)d_in[8];
    const float* fc2_b  = (const float*)d_in[9];
    const float* ada_w  = (const float*)d_in[10];
    const float* ada_b  = (const float*)d_in[11];
    float* out = (float*)d_out;

    float *ada, *x;
    __nv_bfloat16 *hb, *qkvb, *attb, *hidb, *wqb, *wpb, *w1b, *w2b;
    cudaGetSymbolAddress((void**)&ada,  g_ada);
    cudaGetSymbolAddress((void**)&x,    g_x);
    cudaGetSymbolAddress((void**)&hb,   g_hb);
    cudaGetSymbolAddress((void**)&qkvb, g_qkvb);
    cudaGetSymbolAddress((void**)&attb, g_attb);
    cudaGetSymbolAddress((void**)&hidb, g_hidb);
    cudaGetSymbolAddress((void**)&wqb,  g_wqb);
    cudaGetSymbolAddress((void**)&wpb,  g_wpb);
    cudaGetSymbolAddress((void**)&w1b,  g_w1b);
    cudaGetSymbolAddress((void**)&w2b,  g_w2b);

    cudaFuncSetAttribute(mm_gemm<0>, cudaFuncAttributeMaxDynamicSharedMemorySize, MM_SMEM_BYTES);
    cudaFuncSetAttribute(mm_gemm<1>, cudaFuncAttributeMaxDynamicSharedMemorySize, MM_SMEM_BYTES);
    cudaFuncSetAttribute(mm_gemm<2>, cudaFuncAttributeMaxDynamicSharedMemorySize, MM_SMEM_BYTES);
    cudaFuncSetAttribute(mm_gemm<3>, cudaFuncAttributeMaxDynamicSharedMemorySize, MM_SMEM_BYTES);

    // 0) weights -> bf16
    cvtw_kernel<<<(3 * CC * CC / 4 + 255) / 256, 256>>>(qkv_w, wqb, 3 * CC * CC / 4);
    cvtw_kernel<<<(CC * CC / 4 + 255) / 256, 256>>>(proj_w, wpb, CC * CC / 4);
    cvtw_kernel<<<(HIDD * CC / 4 + 255) / 256, 256>>>(fc1_w, w1b, HIDD * CC / 4);
    cvtw_kernel<<<(CC * HIDD / 4 + 255) / 256, 256>>>(fc2_w, w2b, CC * HIDD / 4);
    // 1) adaLN params
    ada_kernel<<<dim3(NB, ADA6 / 128), 128>>>(c, ada_w, ada_b, ada);
    // 2) gather + LN + modulate (MSA) -> bf16
    ln_mod_kernel<0><<<MTOT, 256>>>(x_seq, ada, hb);
    // 3) qkv GEMM (bf16 mma) -> bf16
    mm_gemm<0><<<dim3((3 * CC) / 128, MTOT / 128), 256, MM_SMEM_BYTES>>>(
        hb, wqb, qkv_b, qkvb, 3 * CC, CC, nullptr, nullptr);
    // 4) window attention (bf16 mma) -> bf16
    attn_mma_kernel<<<dim3(MTOT / 64, 12), 128>>>(qkvb, attb);
    // 5) proj GEMM: gate + scattered residual -> g_x (seq order, fp32)
    mm_gemm<1><<<dim3(CC / 128, MTOT / 128), 256, MM_SMEM_BYTES>>>(
        attb, wpb, proj_b, x, CC, CC, ada + 2 * CC, x_seq);
    // 6) LN + modulate (MLP) -> bf16
    ln_mod_kernel<1><<<MTOT, 256>>>(x, ada, hb);
    // 7) fc1 GEMM + GELU -> bf16
    mm_gemm<2><<<dim3(HIDD / 128, MTOT / 128), 256, MM_SMEM_BYTES>>>(
        hb, w1b, fc1_b, hidb, HIDD, CC, nullptr, nullptr);
    // 8) fc2 GEMM + residual + g_mlp gate -> d_out (fp32)
    mm_gemm<3><<<dim3(CC / 128, MTOT / 128), 256, MM_SMEM_BYTES>>>(
        hidb, w2b, fc2_b, out, CC, HIDD, ada + 5 * CC, x);
}

// round 7
// speedup vs baseline: 1.0413x; 1.0413x over previous
#include <cuda_runtime.h>
#include <cuda_bf16.h>
#include <math.h>
#include <stdint.h>

#define NB   8
#define TT   4096
#define CC   768
#define HIDD 3072
#define MTOT (NB * TT)      /* 32768 */
#define ADA6 (6 * CC)       /* 4608  */

// ---------------- scratch (static device globals; allocation-free) ----------
__device__ float g_ada[NB * ADA6];
__device__ float g_x  [(size_t)MTOT * CC];
__device__ __nv_bfloat16 g_hb  [(size_t)MTOT * CC];
__device__ __nv_bfloat16 g_qkvb[(size_t)MTOT * 3 * CC];
__device__ __nv_bfloat16 g_attb[(size_t)MTOT * CC];
__device__ __nv_bfloat16 g_hidb[(size_t)MTOT * HIDD];
__device__ __nv_bfloat16 g_wqb[3 * CC * CC];
__device__ __nv_bfloat16 g_wpb[CC * CC];
__device__ __nv_bfloat16 g_w1b[HIDD * CC];
__device__ __nv_bfloat16 g_w2b[CC * HIDD];

// ---------------- helpers ----------------------------------------------------
__device__ __forceinline__ uint32_t smem_u32(const void* p) {
    uint32_t a;
    asm("{ .reg .u64 t; cvta.to.shared.u64 t, %1; cvt.u32.u64 %0, t; }"
        : "=r"(a) : "l"(p));
    return a;
}

__device__ __forceinline__ void mma_bf16(float* d, const uint32_t* a, const uint32_t* b) {
    asm volatile(
        "mma.sync.aligned.m16n8k16.row.col.f32.bf16.bf16.f32 "
        "{%0,%1,%2,%3}, {%4,%5,%6,%7}, {%8,%9}, {%0,%1,%2,%3};"
        : "+f"(d[0]), "+f"(d[1]), "+f"(d[2]), "+f"(d[3])
        : "r"(a[0]), "r"(a[1]), "r"(a[2]), "r"(a[3]), "r"(b[0]), "r"(b[1]));
}

__device__ __forceinline__ uint32_t packbf(float lo, float hi) {
    __nv_bfloat162 h = __floats2bfloat162_rn(lo, hi);
    return *(uint32_t*)&h;
}

// window(m) -> sequence row index (inverse shift + unpartition)
__device__ __forceinline__ int win2seq(int m) {
    const int nbat = m >> 12, rem = m & 4095, win = rem >> 6, t = rem & 63;
    const int gh = ((win >> 3) << 3) + (t >> 3);
    const int gw = ((win & 7) << 3) + (t & 7);
    return nbat * TT + ((((gh + 4) & 63) << 6) | ((gw + 4) & 63));
}

// ---------------- bf16 mma.sync GEMM (NT): C[M,N]=A[M,K]@B[N,K]^T + bias ----
// CTA 128x128x32, 4-stage cp.async, 8 warps (2x4), warp tile 64x32.
// EPI 0: -> bf16 (qkv). 1: gate + scatter-residual -> fp32 (proj).
// EPI 2: tanh-GELU -> bf16 (fc1). 3: resid + gate -> fp32 (fc2/out).
#define GSTRIDE 20
#define STG_U   (128 * GSTRIDE)
#define NSTG    4
#define MM_SMEM_BYTES (2 * NSTG * STG_U * 4)

template <int EPI>
__global__ void __launch_bounds__(256, 2) mm_gemm(
    const __nv_bfloat16* __restrict__ A, const __nv_bfloat16* __restrict__ B,
    const float* __restrict__ bias, void* __restrict__ Cv,
    int N, int K, const float* __restrict__ gate, const float* __restrict__ resid)
{
    extern __shared__ uint32_t sm[];
    const uint32_t smb = smem_u32(sm);
    const uint32_t BOFF = NSTG * STG_U * 4;
    const int tid = threadIdx.x;
    const int lane = tid & 31, wid = tid >> 5;
    const int g = lane >> 2, t4 = lane & 3;
    const int warpM = wid >> 2, warpN = wid & 3;
    const int n0 = blockIdx.x * 128, m0 = blockIdx.y * 128;
    const int nk = K >> 5;

    float acc[4][4][4];
    #pragma unroll
    for (int i = 0; i < 4; i++)
        #pragma unroll
        for (int j = 0; j < 4; j++)
            #pragma unroll
            for (int q = 0; q < 4; q++) acc[i][j][q] = 0.0f;

    auto load_stage = [&](int s, int kk) {
        const int k0 = kk << 5;
        #pragma unroll
        for (int j = 0; j < 2; j++) {
            const int f = tid + (j << 8);
            const int r = f >> 2, q = f & 3;
            const __nv_bfloat16* srcA = A + (size_t)(m0 + r) * K + k0 + (q << 3);
            const __nv_bfloat16* srcB = B + (size_t)(n0 + r) * K + k0 + (q << 3);
            const uint32_t off = (uint32_t)(s * STG_U + r * GSTRIDE + (q << 2)) << 2;
            asm volatile("cp.async.cg.shared.global [%0], [%1], 16;"
                         :: "r"(smb + off), "l"(srcA));
            asm volatile("cp.async.cg.shared.global [%0], [%1], 16;"
                         :: "r"(smb + BOFF + off), "l"(srcB));
        }
        asm volatile("cp.async.commit_group;" ::: "memory");
    };

    load_stage(0, 0);
    load_stage(1, 1);
    load_stage(2, 2);

    int s = 0;
    for (int kk = 0; kk < nk; kk++) {
        if (kk + 1 < nk) asm volatile("cp.async.wait_group 2;" ::: "memory");
        else             asm volatile("cp.async.wait_group 0;" ::: "memory");
        __syncthreads();
        if (kk + 3 < nk) load_stage((s + 3) & 3, kk + 3);

        const uint32_t* Asb = sm + s * STG_U;
        const uint32_t* Bsb = sm + NSTG * STG_U + s * STG_U;
        #pragma unroll
        for (int ks = 0; ks < 2; ks++) {
            const int kc = ks << 3;
            uint32_t a[4][4], b[4][2];
            #pragma unroll
            for (int i = 0; i < 4; i++) {
                const int mb = warpM * 64 + i * 16;
                a[i][0] = Asb[(mb + g    ) * GSTRIDE + kc + t4    ];
                a[i][1] = Asb[(mb + g + 8) * GSTRIDE + kc + t4    ];
                a[i][2] = Asb[(mb + g    ) * GSTRIDE + kc + t4 + 4];
                a[i][3] = Asb[(mb + g + 8) * GSTRIDE + kc + t4 + 4];
            }
            #pragma unroll
            for (int j = 0; j < 4; j++) {
                const int nb = warpN * 32 + j * 8;
                b[j][0] = Bsb[(nb + g) * GSTRIDE + kc + t4    ];
                b[j][1] = Bsb[(nb + g) * GSTRIDE + kc + t4 + 4];
            }
            #pragma unroll
            for (int i = 0; i < 4; i++)
                #pragma unroll
                for (int j = 0; j < 4; j++)
                    mma_bf16(acc[i][j], a[i], b[j]);
        }
        s = (s + 1) & 3;
    }

    // ---------------- epilogue ------------------------------------------------
    const int batch = m0 >> 12;
    const float* gbase = (EPI == 1 || EPI == 3) ? (gate + batch * ADA6) : nullptr;
    #pragma unroll
    for (int i = 0; i < 4; i++) {
        #pragma unroll
        for (int h2 = 0; h2 < 2; h2++) {
            const int row = m0 + warpM * 64 + i * 16 + g + h2 * 8;
            const int srow = (EPI == 1) ? win2seq(row) : row;
            const float* rrow = (EPI == 1 || EPI == 3)
                                ? (resid + (size_t)srow * N) : nullptr;
            #pragma unroll
            for (int j = 0; j < 4; j++) {
                const int nc = n0 + warpN * 32 + j * 8 + t4 * 2;
                float v0 = acc[i][j][h2 * 2 + 0] + bias[nc];
                float v1 = acc[i][j][h2 * 2 + 1] + bias[nc + 1];
                if (EPI == 1) {
                    v0 = rrow[nc]     + gbase[nc]     * v0;
                    v1 = rrow[nc + 1] + gbase[nc + 1] * v1;
                } else if (EPI == 2) {
                    float u0 = 0.7978845608028654f * (v0 + 0.044715f * v0 * v0 * v0);
                    float u1 = 0.7978845608028654f * (v1 + 0.044715f * v1 * v1 * v1);
                    v0 = __fdividef(v0, 1.0f + __expf(-2.0f * u0));
                    v1 = __fdividef(v1, 1.0f + __expf(-2.0f * u1));
                } else if (EPI == 3) {
                    v0 = rrow[nc]     + gbase[nc]     * v0;
                    v1 = rrow[nc + 1] + gbase[nc + 1] * v1;
                }
                if (EPI == 0 || EPI == 2) {
                    __nv_bfloat16* crow = (__nv_bfloat16*)Cv + (size_t)row * N;
                    __nv_bfloat162 h = __floats2bfloat162_rn(v0, v1);
                    *(__nv_bfloat162*)(crow + nc) = h;
                } else {
                    float* crow = (float*)Cv + (size_t)srow * N;
                    *(float2*)(crow + nc) = make_float2(v0, v1);
                }
            }
        }
    }
}

// ---------------- all 4 weight conversions in ONE launch ----------------------
#define WQ4 (3 * CC * CC / 4)
#define WP4 (CC * CC / 4)
#define W14 (HIDD * CC / 4)
#define W24 (CC * HIDD / 4)
__global__ void __launch_bounds__(256) cvtw_all_kernel(
    const float* __restrict__ s0, __nv_bfloat16* __restrict__ d0,
    const float* __restrict__ s1, __nv_bfloat16* __restrict__ d1,
    const float* __restrict__ s2, __nv_bfloat16* __restrict__ d2,
    const float* __restrict__ s3, __nv_bfloat16* __restrict__ d3)
{
    int i = blockIdx.x * 256 + threadIdx.x;
    const float* src;
    __nv_bfloat16* dst;
    if (i < WQ4)                      { src = s0; dst = d0; }
    else if ((i -= WQ4) < WP4)        { src = s1; dst = d1; }
    else if ((i -= WP4) < W14)        { src = s2; dst = d2; }
    else if ((i -= W14) < W24)        { src = s3; dst = d3; }
    else return;
    float4 v = ((const float4*)src)[i];
    ((__nv_bfloat162*)dst)[i * 2]     = __floats2bfloat162_rn(v.x, v.y);
    ((__nv_bfloat162*)dst)[i * 2 + 1] = __floats2bfloat162_rn(v.z, v.w);
}

// ---------------- adaLN: ada = silu(c) @ ada_w^T + ada_b --------------------
__global__ void __launch_bounds__(128) ada_kernel(
    const float* __restrict__ c, const float* __restrict__ w,
    const float* __restrict__ b, float* __restrict__ ada)
{
    __shared__ float sc[CC];
    const int n = blockIdx.x, tid = threadIdx.x;
    for (int i = tid; i < CC; i += 128) {
        float x = c[n * CC + i];
        sc[i] = x / (1.0f + expf(-x));
    }
    __syncthreads();
    const int j = blockIdx.y * 128 + tid;
    const float* wr = w + (size_t)j * CC;
    float acc = b[j];
    #pragma unroll 8
    for (int k = 0; k < CC; k++) acc += sc[k] * wr[k];
    ada[n * ADA6 + j] = acc;
}

// ---------------- LN + modulate -> bf16 (warp-shuffle reduction) -------------
template <int MODE>
__global__ void __launch_bounds__(256) ln_mod_kernel(
    const float* __restrict__ xin, const float* __restrict__ ada,
    __nv_bfloat16* __restrict__ out)
{
    const int m = blockIdx.x, tid = threadIdx.x;
    const int lane = tid & 31, wrp = tid >> 5;
    const int n = m >> 12;
    const float* xr = (MODE == 0) ? (xin + (size_t)win2seq(m) * CC)
                                  : (xin + (size_t)m * CC);
    const float v0 = xr[tid], v1 = xr[tid + 256], v2 = xr[tid + 512];
    float ss = v0 + v1 + v2;
    float sq = v0 * v0 + v1 * v1 + v2 * v2;
    #pragma unroll
    for (int o = 16; o > 0; o >>= 1) {
        ss += __shfl_xor_sync(0xffffffffu, ss, o);
        sq += __shfl_xor_sync(0xffffffffu, sq, o);
    }
    __shared__ float ps[8], pq[8];
    if (lane == 0) { ps[wrp] = ss; pq[wrp] = sq; }
    __syncthreads();
    float ts = 0.0f, tq = 0.0f;
    #pragma unroll
    for (int w2 = 0; w2 < 8; w2++) { ts += ps[w2]; tq += pq[w2]; }
    const float mean = ts * (1.0f / CC);
    const float var  = tq * (1.0f / CC) - mean * mean;
    const float rstd = rsqrtf(var + 1e-6f);
    const float* shv = ada + n * ADA6 + (MODE == 0 ? 0 : 3 * CC);
    const float* scv = ada + n * ADA6 + (MODE == 0 ? CC : 4 * CC);
    const size_t ob = (size_t)m * CC;
    out[ob + tid      ] = __float2bfloat16_rn((v0 - mean) * rstd * (1.0f + scv[tid      ]) + shv[tid      ]);
    out[ob + tid + 256] = __float2bfloat16_rn((v1 - mean) * rstd * (1.0f + scv[tid + 256]) + shv[tid + 256]);
    out[ob + tid + 512] = __float2bfloat16_rn((v2 - mean) * rstd * (1.0f + scv[tid + 512]) + shv[tid + 512]);
}

// ---------------- window attention (bf16 mma.sync) ---------------------------
#define APAD 72
__global__ void __launch_bounds__(128) attn_mma_kernel(
    const __nv_bfloat16* __restrict__ qkv, __nv_bfloat16* __restrict__ out)
{
    __shared__ __nv_bfloat16 sq [64 * APAD];
    __shared__ __nv_bfloat16 sk [64 * APAD];
    __shared__ __nv_bfloat16 svt[64 * APAD];   // V transposed: [d][c]
    const int b = blockIdx.x, hh = blockIdx.y;
    const int tid = threadIdx.x, lane = tid & 31, wid = tid >> 5;
    const int g = lane >> 2, t = lane & 3;
    const __nv_bfloat16* base = qkv + (size_t)b * 64 * (3 * CC) + hh * 64;

    {
        const int r = tid >> 1;
        const __nv_bfloat162 s8 = __floats2bfloat162_rn(0.125f, 0.125f);
        #pragma unroll
        for (int i = 0; i < 4; i++) {
            const int c0 = ((tid & 1) << 5) + (i << 3);
            uint4 vq = *(const uint4*)(base + (size_t)r * (3 * CC) + c0);
            __nv_bfloat162* pq = (__nv_bfloat162*)&vq;
            pq[0] = __hmul2(pq[0], s8); pq[1] = __hmul2(pq[1], s8);
            pq[2] = __hmul2(pq[2], s8); pq[3] = __hmul2(pq[3], s8);
            *(uint4*)(sq + r * APAD + c0) = vq;
            uint4 vk = *(const uint4*)(base + (size_t)r * (3 * CC) + CC + c0);
            *(uint4*)(sk + r * APAD + c0) = vk;
            uint4 vv = *(const uint4*)(base + (size_t)r * (3 * CC) + 2 * CC + c0);
            const __nv_bfloat16* hv = (const __nv_bfloat16*)&vv;
            #pragma unroll
            for (int q2 = 0; q2 < 8; q2++)
                svt[(c0 + q2) * APAD + r] = hv[q2];
        }
    }
    __syncthreads();

    const uint32_t* sq32 = (const uint32_t*)sq;
    const uint32_t* sk32 = (const uint32_t*)sk;
    const uint32_t* sv32 = (const uint32_t*)svt;
    const int mb = wid << 4;
    const int RS = APAD / 2;

    float accS[8][4];
    #pragma unroll
    for (int j = 0; j < 8; j++)
        #pragma unroll
        for (int q = 0; q < 4; q++) accS[j][q] = 0.0f;
    #pragma unroll
    for (int ks = 0; ks < 4; ks++) {
        const int kc = ks << 3;
        uint32_t a[4];
        a[0] = sq32[(mb + g    ) * RS + kc + t    ];
        a[1] = sq32[(mb + g + 8) * RS + kc + t    ];
        a[2] = sq32[(mb + g    ) * RS + kc + t + 4];
        a[3] = sq32[(mb + g + 8) * RS + kc + t + 4];
        #pragma unroll
        for (int j = 0; j < 8; j++) {
            uint32_t bb[2];
            bb[0] = sk32[((j << 3) + g) * RS + kc + t    ];
            bb[1] = sk32[((j << 3) + g) * RS + kc + t + 4];
            mma_bf16(accS[j], a, bb);
        }
    }

    float mx0 = -1e30f, mx1 = -1e30f;
    #pragma unroll
    for (int j = 0; j < 8; j++) {
        mx0 = fmaxf(mx0, fmaxf(accS[j][0], accS[j][1]));
        mx1 = fmaxf(mx1, fmaxf(accS[j][2], accS[j][3]));
    }
    mx0 = fmaxf(mx0, __shfl_xor_sync(0xffffffffu, mx0, 1));
    mx0 = fmaxf(mx0, __shfl_xor_sync(0xffffffffu, mx0, 2));
    mx1 = fmaxf(mx1, __shfl_xor_sync(0xffffffffu, mx1, 1));
    mx1 = fmaxf(mx1, __shfl_xor_sync(0xffffffffu, mx1, 2));
    float sum0 = 0.0f, sum1 = 0.0f;
    #pragma unroll
    for (int j = 0; j < 8; j++) {
        accS[j][0] = __expf(accS[j][0] - mx0);
        accS[j][1] = __expf(accS[j][1] - mx0);
        accS[j][2] = __expf(accS[j][2] - mx1);
        accS[j][3] = __expf(accS[j][3] - mx1);
        sum0 += accS[j][0] + accS[j][1];
        sum1 += accS[j][2] + accS[j][3];
    }
    sum0 += __shfl_xor_sync(0xffffffffu, sum0, 1);
    sum0 += __shfl_xor_sync(0xffffffffu, sum0, 2);
    sum1 += __shfl_xor_sync(0xffffffffu, sum1, 1);
    sum1 += __shfl_xor_sync(0xffffffffu, sum1, 2);
    const float inv0 = 1.0f / sum0, inv1 = 1.0f / sum1;

    uint32_t pa[4][4];
    #pragma unroll
    for (int ks = 0; ks < 4; ks++) {
        pa[ks][0] = packbf(accS[2 * ks][0],     accS[2 * ks][1]);
        pa[ks][1] = packbf(accS[2 * ks][2],     accS[2 * ks][3]);
        pa[ks][2] = packbf(accS[2 * ks + 1][0], accS[2 * ks + 1][1]);
        pa[ks][3] = packbf(accS[2 * ks + 1][2], accS[2 * ks + 1][3]);
    }

    float accO[8][4];
    #pragma unroll
    for (int j = 0; j < 8; j++)
        #pragma unroll
        for (int q = 0; q < 4; q++) accO[j][q] = 0.0f;
    #pragma unroll
    for (int ks = 0; ks < 4; ks++) {
        const int kc = ks << 3;
        #pragma unroll
        for (int j = 0; j < 8; j++) {
            uint32_t bb[2];
            bb[0] = sv32[((j << 3) + g) * RS + kc + t    ];
            bb[1] = sv32[((j << 3) + g) * RS + kc + t + 4];
            mma_bf16(accO[j], pa[ks], bb);
        }
    }

    __nv_bfloat16* orow0 = out + ((size_t)b * 64 + mb + g    ) * CC + hh * 64;
    __nv_bfloat16* orow1 = out + ((size_t)b * 64 + mb + g + 8) * CC + hh * 64;
    #pragma unroll
    for (int j = 0; j < 8; j++) {
        const int dc = (j << 3) + (t << 1);
        *(uint32_t*)(orow0 + dc) = packbf(accO[j][0] * inv0, accO[j][1] * inv0);
        *(uint32_t*)(orow1 + dc) = packbf(accO[j][2] * inv1, accO[j][3] * inv1);
    }
}

// ---------------- launch ------------------------------------------------------
extern "C" void kernel_launch(void* const* d_in, const int* in_sizes, int n_in,
                              void* d_out, int out_size)
{
    const float* x_seq  = (const float*)d_in[0];
    const float* c      = (const float*)d_in[1];
    const float* qkv_w  = (const float*)d_in[2];
    const float* qkv_b  = (const float*)d_in[3];
    const float* proj_w = (const float*)d_in[4];
    const float* proj_b = (const float*)d_in[5];
    const float* fc1_w  = (const float*)d_in[6];
    const float* fc1_b  = (const float*)d_in[7];
    const float* fc2_w  = (const float*)d_in[8];
    const float* fc2_b  = (const float*)d_in[9];
    const float* ada_w  = (const float*)d_in[10];
    const float* ada_b  = (const float*)d_in[11];
    float* out = (float*)d_out;

    float *ada, *x;
    __nv_bfloat16 *hb, *qkvb, *attb, *hidb, *wqb, *wpb, *w1b, *w2b;
    cudaGetSymbolAddress((void**)&ada,  g_ada);
    cudaGetSymbolAddress((void**)&x,    g_x);
    cudaGetSymbolAddress((void**)&hb,   g_hb);
    cudaGetSymbolAddress((void**)&qkvb, g_qkvb);
    cudaGetSymbolAddress((void**)&attb, g_attb);
    cudaGetSymbolAddress((void**)&hidb, g_hidb);
    cudaGetSymbolAddress((void**)&wqb,  g_wqb);
    cudaGetSymbolAddress((void**)&wpb,  g_wpb);
    cudaGetSymbolAddress((void**)&w1b,  g_w1b);
    cudaGetSymbolAddress((void**)&w2b,  g_w2b);

    cudaFuncSetAttribute(mm_gemm<0>, cudaFuncAttributeMaxDynamicSharedMemorySize, MM_SMEM_BYTES);
    cudaFuncSetAttribute(mm_gemm<1>, cudaFuncAttributeMaxDynamicSharedMemorySize, MM_SMEM_BYTES);
    cudaFuncSetAttribute(mm_gemm<2>, cudaFuncAttributeMaxDynamicSharedMemorySize, MM_SMEM_BYTES);
    cudaFuncSetAttribute(mm_gemm<3>, cudaFuncAttributeMaxDynamicSharedMemorySize, MM_SMEM_BYTES);

    // 0) all weights -> bf16 (single launch)
    cvtw_all_kernel<<<(WQ4 + WP4 + W14 + W24 + 255) / 256, 256>>>(
        qkv_w, wqb, proj_w, wpb, fc1_w, w1b, fc2_w, w2b);
    // 1) adaLN params
    ada_kernel<<<dim3(NB, ADA6 / 128), 128>>>(c, ada_w, ada_b, ada);
    // 2) gather + LN + modulate (MSA) -> bf16
    ln_mod_kernel<0><<<MTOT, 256>>>(x_seq, ada, hb);
    // 3) qkv GEMM (bf16 mma) -> bf16
    mm_gemm<0><<<dim3((3 * CC) / 128, MTOT / 128), 256, MM_SMEM_BYTES>>>(
        hb, wqb, qkv_b, qkvb, 3 * CC, CC, nullptr, nullptr);
    // 4) window attention (bf16 mma) -> bf16
    attn_mma_kernel<<<dim3(MTOT / 64, 12), 128>>>(qkvb, attb);
    // 5) proj GEMM: gate + scattered residual -> g_x (seq order, fp32)
    mm_gemm<1><<<dim3(CC / 128, MTOT / 128), 256, MM_SMEM_BYTES>>>(
        attb, wpb, proj_b, x, CC, CC, ada + 2 * CC, x_seq);
    // 6) LN + modulate (MLP) -> bf16
    ln_mod_kernel<1><<<MTOT, 256>>>(x, ada, hb);
    // 7) fc1 GEMM + GELU -> bf16
    mm_gemm<2><<<dim3(HIDD / 128, MTOT / 128), 256, MM_SMEM_BYTES>>>(
        hb, w1b, fc1_b, hidb, HIDD, CC, nullptr, nullptr);
    // 8) fc2 GEMM + residual + g_mlp gate -> d_out (fp32)
    mm_gemm<3><<<dim3(CC / 128, MTOT / 128), 256, MM_SMEM_BYTES>>>(
        hidb, w2b, fc2_b, out, CC, HIDD, ada + 5 * CC, x);
}